// round 1
// baseline (speedup 1.0000x reference)
#include <cuda_runtime.h>
#include <math.h>

#define BB 8
#define S1 4096
#define S2 256
#define NH 16
#define HD 64
#define QD 1024
#define KVD 2048
#define EPSF 1e-6f
#define SCALEF 0.125f
#define AR 128

// Scratch (device globals — no allocation allowed)
__device__ float g_q[(size_t)BB * S1 * QD];    // Q after GEMM, then LN+RoPE in place (b,s1,nh,hd)
__device__ float g_kv[(size_t)BB * S2 * KVD];  // KV after GEMM, LN(k) in place
__device__ float g_att[(size_t)BB * S1 * QD];  // attention output (b,s1,nh,hd)

// ---------------------------------------------------------------------------
// Generic C = A @ W^T + bias   A:(M,K) row-major, W:(N,K) row-major, C:(M,N)
// 128x128 tile, BK=8, 256 threads, 8x8 micro-tile.
// M % 128 == 0, N % 128 == 0, K % 8 == 0 for all call sites.
// ---------------------------------------------------------------------------
__global__ __launch_bounds__(256) void gemm_bias(
    const float* __restrict__ A, const float* __restrict__ W,
    const float* __restrict__ bias, float* __restrict__ C,
    int M, int N, int K)
{
    __shared__ float As[8][128];
    __shared__ float Bs[8][128];
    int tid = threadIdx.x;
    int tx = tid & 15, ty = tid >> 4;
    const float* Ab = A + (size_t)blockIdx.y * 128 * K;
    const float* Wb = W + (size_t)blockIdx.x * 128 * K;
    int lrow = tid >> 1;          // 0..127
    int lseg = (tid & 1) * 4;     // 0 or 4

    float acc[8][8];
#pragma unroll
    for (int i = 0; i < 8; i++)
#pragma unroll
        for (int j = 0; j < 8; j++) acc[i][j] = 0.0f;

    for (int kt = 0; kt < K; kt += 8) {
        float4 av = *(const float4*)(Ab + (size_t)lrow * K + kt + lseg);
        float4 wv = *(const float4*)(Wb + (size_t)lrow * K + kt + lseg);
        As[lseg + 0][lrow] = av.x; As[lseg + 1][lrow] = av.y;
        As[lseg + 2][lrow] = av.z; As[lseg + 3][lrow] = av.w;
        Bs[lseg + 0][lrow] = wv.x; Bs[lseg + 1][lrow] = wv.y;
        Bs[lseg + 2][lrow] = wv.z; Bs[lseg + 3][lrow] = wv.w;
        __syncthreads();
#pragma unroll
        for (int c = 0; c < 8; c++) {
            float a[8], b[8];
            *(float4*)&a[0] = *(const float4*)&As[c][ty * 8];
            *(float4*)&a[4] = *(const float4*)&As[c][ty * 8 + 4];
            *(float4*)&b[0] = *(const float4*)&Bs[c][tx * 8];
            *(float4*)&b[4] = *(const float4*)&Bs[c][tx * 8 + 4];
#pragma unroll
            for (int i = 0; i < 8; i++)
#pragma unroll
                for (int j = 0; j < 8; j++) acc[i][j] += a[i] * b[j];
        }
        __syncthreads();
    }

    int col0 = blockIdx.x * 128 + tx * 8;
    float bv[8];
    *(float4*)&bv[0] = *(const float4*)&bias[col0];
    *(float4*)&bv[4] = *(const float4*)&bias[col0 + 4];
#pragma unroll
    for (int i = 0; i < 8; i++) {
        size_t row = (size_t)blockIdx.y * 128 + ty * 8 + i;
        float4 o0 = make_float4(acc[i][0] + bv[0], acc[i][1] + bv[1],
                                acc[i][2] + bv[2], acc[i][3] + bv[3]);
        float4 o1 = make_float4(acc[i][4] + bv[4], acc[i][5] + bv[5],
                                acc[i][6] + bv[6], acc[i][7] + bv[7]);
        *(float4*)(C + row * N + col0) = o0;
        *(float4*)(C + row * N + col0 + 4) = o1;
    }
}

// ---------------------------------------------------------------------------
// LayerNorm (per 64-dim head chunk) + 2D RoPE on Q, in place.
// One warp per (b, s, h) chunk; each lane owns the pair (2*lane, 2*lane+1).
// ---------------------------------------------------------------------------
__global__ void ln_rope_q(float* __restrict__ q,
                          const float* __restrict__ g, const float* __restrict__ bt)
{
    int gw = (blockIdx.x * blockDim.x + threadIdx.x) >> 5;
    int lane = threadIdx.x & 31;
    if (gw >= BB * S1 * NH) return;
    float2* p = (float2*)(q + (size_t)gw * HD);
    float2 v = p[lane];
    float sum = v.x + v.y;
    float sq = v.x * v.x + v.y * v.y;
#pragma unroll
    for (int o = 16; o; o >>= 1) {
        sum += __shfl_xor_sync(0xffffffffu, sum, o);
        sq  += __shfl_xor_sync(0xffffffffu, sq, o);
    }
    float mu = sum * (1.0f / HD);
    float var = sq * (1.0f / HD) - mu * mu;
    float rstd = rsqrtf(var + EPSF);
    float e  = (v.x - mu) * rstd * g[2 * lane]     + bt[2 * lane];
    float od = (v.y - mu) * rstd * g[2 * lane + 1] + bt[2 * lane + 1];

    int s = (gw / NH) & (S1 - 1);
    int hh = s >> 6, ww = s & 63;
    int t = lane >> 1;
    float inv = exp10f(-0.25f * (float)t);                  // 10000^(-t/16)
    float ang = ((lane & 1) ? (float)ww : (float)hh) * inv;
    // safe range reduction (robust even under fast-math sincos)
    float n = rintf(ang * 0.15915494309189535f);
    ang -= n * 6.283185307179586f;
    float sn, cs;
    sincosf(ang, &sn, &cs);
    p[lane] = make_float2(e * cs - od * sn, e * sn + od * cs);
}

// LayerNorm on K (first QD columns of KV), in place. One warp per (b, s2, h).
__global__ void ln_k(float* __restrict__ kv,
                     const float* __restrict__ g, const float* __restrict__ bt)
{
    int gw = (blockIdx.x * blockDim.x + threadIdx.x) >> 5;
    int lane = threadIdx.x & 31;
    if (gw >= BB * S2 * NH) return;
    int row = gw / NH, h = gw % NH;
    float2* p = (float2*)(kv + (size_t)row * KVD + h * HD);
    float2 v = p[lane];
    float sum = v.x + v.y;
    float sq = v.x * v.x + v.y * v.y;
#pragma unroll
    for (int o = 16; o; o >>= 1) {
        sum += __shfl_xor_sync(0xffffffffu, sum, o);
        sq  += __shfl_xor_sync(0xffffffffu, sq, o);
    }
    float mu = sum * (1.0f / HD);
    float var = sq * (1.0f / HD) - mu * mu;
    float rstd = rsqrtf(var + EPSF);
    float e  = (v.x - mu) * rstd * g[2 * lane]     + bt[2 * lane];
    float od = (v.y - mu) * rstd * g[2 * lane + 1] + bt[2 * lane + 1];
    p[lane] = make_float2(e, od);
}

// ---------------------------------------------------------------------------
// Attention: one block = 128 query rows of one (b,h). S2=256 keys.
// smem: Qs[128][64], Ks[256][65] (reused for V), Ss[128][256]  -> 230400 B
// Each of the 256 threads owns one key (register-resident 64-float vector).
// ---------------------------------------------------------------------------
__global__ __launch_bounds__(256) void attention_kernel(
    const float* __restrict__ q, const float* __restrict__ kv,
    float* __restrict__ out)
{
    extern __shared__ float sm[];
    float* Qs = sm;                 // AR*HD
    float* Ks = sm + AR * HD;       // S2*65  (V later)
    float* Ss = Ks + S2 * 65;       // AR*S2
    int bh = blockIdx.y;
    int b = bh >> 4, h = bh & 15;
    int r0 = blockIdx.x * AR;
    int tid = threadIdx.x;

    for (int i = tid; i < AR * HD; i += 256) {
        int r = i >> 6, d = i & 63;
        Qs[i] = q[(((size_t)b * S1 + r0 + r) * NH + h) * HD + d];
    }
    for (int i = tid; i < S2 * HD; i += 256) {
        int k = i >> 6, d = i & 63;
        Ks[k * 65 + d] = kv[((size_t)b * S2 + k) * KVD + h * HD + d];
    }
    __syncthreads();

    // This thread's key vector -> registers
    float kreg[64];
#pragma unroll
    for (int d = 0; d < 64; d++) kreg[d] = Ks[tid * 65 + d];

    // scores: Ss[r][tid] = scale * <Q[r], K[tid]>
    for (int r = 0; r < AR; r += 2) {
        const float* q0 = Qs + r * 64;
        const float* q1 = q0 + 64;
        float a0 = 0, a1 = 0, c0 = 0, c1 = 0;
#pragma unroll
        for (int d = 0; d < 64; d += 2) {
            a0 += q0[d] * kreg[d];     a1 += q0[d + 1] * kreg[d + 1];
            c0 += q1[d] * kreg[d];     c1 += q1[d + 1] * kreg[d + 1];
        }
        Ss[r * 256 + tid]       = (a0 + a1) * SCALEF;
        Ss[(r + 1) * 256 + tid] = (c0 + c1) * SCALEF;
    }
    __syncthreads();

    // softmax: warp per row, 8 values per lane
    int wid = tid >> 5, lane = tid & 31;
    for (int r = wid; r < AR; r += 8) {
        float* srow = Ss + r * 256;
        float vals[8];
        float m = -1e30f;
#pragma unroll
        for (int i = 0; i < 8; i++) { vals[i] = srow[lane + 32 * i]; m = fmaxf(m, vals[i]); }
#pragma unroll
        for (int o = 16; o; o >>= 1) m = fmaxf(m, __shfl_xor_sync(0xffffffffu, m, o));
        float l = 0;
#pragma unroll
        for (int i = 0; i < 8; i++) { vals[i] = __expf(vals[i] - m); l += vals[i]; }
#pragma unroll
        for (int o = 16; o; o >>= 1) l += __shfl_xor_sync(0xffffffffu, l, o);
        float rl = 1.0f / l;
#pragma unroll
        for (int i = 0; i < 8; i++) srow[lane + 32 * i] = vals[i] * rl;
    }
    __syncthreads();

    // V overwrites the K smem region
    for (int i = tid; i < S2 * HD; i += 256) {
        int k = i >> 6, d = i & 63;
        Ks[k * 65 + d] = kv[((size_t)b * S2 + k) * KVD + QD + h * HD + d];
    }
    __syncthreads();

    // PV: thread owns columns (lane, lane+32); warp `wid` handles rows wid+8*i
    int d0 = lane, d1 = lane + 32;
    for (int i = 0; i < 16; i++) {
        int r = wid + 8 * i;
        const float* srow = Ss + r * 256;
        float acc0 = 0, acc1 = 0;
#pragma unroll 8
        for (int k = 0; k < 256; k++) {
            float pv = srow[k];
            acc0 += pv * Ks[k * 65 + d0];
            acc1 += pv * Ks[k * 65 + d1];
        }
        size_t ob = (((size_t)b * S1 + r0 + r) * NH + h) * HD;
        out[ob + d0] = acc0;
        out[ob + d1] = acc1;
    }
}

// ---------------------------------------------------------------------------
extern "C" void kernel_launch(void* const* d_in, const int* in_sizes, int n_in,
                              void* d_out, int out_size)
{
    (void)in_sizes; (void)n_in; (void)out_size;
    const float* x   = (const float*)d_in[0];
    const float* y   = (const float*)d_in[1];
    const float* wq  = (const float*)d_in[2];
    const float* bq  = (const float*)d_in[3];
    const float* wkv = (const float*)d_in[4];
    const float* bkv = (const float*)d_in[5];
    const float* wo  = (const float*)d_in[6];
    const float* bo  = (const float*)d_in[7];
    const float* qng = (const float*)d_in[8];
    const float* qnb = (const float*)d_in[9];
    const float* kng = (const float*)d_in[10];
    const float* knb = (const float*)d_in[11];
    float* out = (float*)d_out;

    float *qbuf, *kvbuf, *abuf;
    cudaGetSymbolAddress((void**)&qbuf, g_q);
    cudaGetSymbolAddress((void**)&kvbuf, g_kv);
    cudaGetSymbolAddress((void**)&abuf, g_att);

    // 1) Q = x @ wq^T + bq
    gemm_bias<<<dim3(QD / 128, (BB * S1) / 128), 256>>>(x, wq, bq, qbuf, BB * S1, QD, QD);
    // 2) KV = y @ wkv^T + bkv
    gemm_bias<<<dim3(KVD / 128, (BB * S2) / 128), 256>>>(y, wkv, bkv, kvbuf, BB * S2, KVD, KVD);
    // 3) LN + RoPE on Q (in place)
    {
        int warps = BB * S1 * NH;
        ln_rope_q<<<warps / 4, 128>>>(qbuf, qng, qnb);
    }
    // 4) LN on K (in place)
    {
        int warps = BB * S2 * NH;
        ln_k<<<warps / 4, 128>>>(kvbuf, kng, knb);
    }
    // 5) attention
    {
        size_t smem = (size_t)(AR * HD + S2 * 65 + AR * S2) * sizeof(float); // 230400
        cudaFuncSetAttribute(attention_kernel,
                             cudaFuncAttributeMaxDynamicSharedMemorySize, (int)smem);
        attention_kernel<<<dim3(S1 / AR, BB * NH), 256, smem>>>(qbuf, kvbuf, abuf);
    }
    // 6) out = att @ wo^T + bo
    gemm_bias<<<dim3(QD / 128, (BB * S1) / 128), 256>>>(abuf, wo, bo, out, BB * S1, QD, QD);
}

// round 2
// speedup vs baseline: 1.3747x; 1.3747x over previous
#include <cuda_runtime.h>
#include <cuda_bf16.h>
#include <math.h>

#define BB 8
#define S1 4096
#define S2 256
#define NH 16
#define HD 64
#define QD 1024
#define KVD 2048
#define EPSF 1e-6f
#define SCALEF 0.125f
#define AR 128

// Scratch (device globals — no allocation allowed)
__device__ float g_q[(size_t)BB * S1 * QD];
__device__ float g_kv[(size_t)BB * S2 * KVD];
__device__ float g_att[(size_t)BB * S1 * QD];

// ---------------------------------------------------------------------------
// bf16 split-precision tensor-core GEMM:  C = A @ W^T + bias
// A:(M,K) row-major fp32, W:(N,K) row-major fp32, C:(M,N) fp32.
// Each fp32 is split a = a_hi + a_lo (bf16); product uses 3 MMAs:
//   hi*hi + lo*hi + hi*lo  (dropped lo*lo ~ 2^-18 relative)
// Tile: 128x128, BK=32. 256 threads = 8 warps (4 along M x 2 along N),
// warp tile 32x64 -> 2x8 m16n8k16 fragments.
// ---------------------------------------------------------------------------
#define PADK 40  // 32 + 8 halves padding: conflict-free fragment loads

__device__ __forceinline__ void mma16816(float* c, const unsigned* a, const unsigned* b)
{
    asm volatile(
        "mma.sync.aligned.m16n8k16.row.col.f32.bf16.bf16.f32 "
        "{%0,%1,%2,%3}, {%4,%5,%6,%7}, {%8,%9}, {%0,%1,%2,%3};"
        : "+f"(c[0]), "+f"(c[1]), "+f"(c[2]), "+f"(c[3])
        : "r"(a[0]), "r"(a[1]), "r"(a[2]), "r"(a[3]), "r"(b[0]), "r"(b[1]));
}

__device__ __forceinline__ unsigned pack_bf16(__nv_bfloat16 lo, __nv_bfloat16 hi)
{
    return (unsigned)__bfloat16_as_ushort(lo) | ((unsigned)__bfloat16_as_ushort(hi) << 16);
}

__global__ __launch_bounds__(256) void gemm_bias_tc(
    const float* __restrict__ A, const float* __restrict__ W,
    const float* __restrict__ bias, float* __restrict__ C,
    int M, int N, int K)
{
    __shared__ __nv_bfloat16 As_hi[128 * PADK];
    __shared__ __nv_bfloat16 As_lo[128 * PADK];
    __shared__ __nv_bfloat16 Bs_hi[128 * PADK];
    __shared__ __nv_bfloat16 Bs_lo[128 * PADK];

    int tid = threadIdx.x;
    int wid = tid >> 5, lane = tid & 31;
    int wm = wid & 3, wn = wid >> 2;       // 4 warps over M(32 each), 2 over N(64 each)
    int g = lane >> 2, t = lane & 3;

    const float* Ab = A + (size_t)blockIdx.y * 128 * K;
    const float* Wb = W + (size_t)blockIdx.x * 128 * K;

    float acc[2][8][4];
#pragma unroll
    for (int mi = 0; mi < 2; mi++)
#pragma unroll
        for (int ni = 0; ni < 8; ni++)
#pragma unroll
            for (int r = 0; r < 4; r++) acc[mi][ni][r] = 0.0f;

    // per-thread staging: 4 float4 from A tile, 4 from W tile
    int srow[4], sc4[4];
#pragma unroll
    for (int i = 0; i < 4; i++) {
        int idx = tid + i * 256;           // 0..1023
        srow[i] = idx >> 3;
        sc4[i] = (idx & 7) * 4;
    }

    float4 av[4], bv[4];
#pragma unroll
    for (int i = 0; i < 4; i++) {
        av[i] = *(const float4*)(Ab + (size_t)srow[i] * K + sc4[i]);
        bv[i] = *(const float4*)(Wb + (size_t)srow[i] * K + sc4[i]);
    }

    for (int kt = 0; kt < K; kt += 32) {
        // split + store staged chunk to smem
#pragma unroll
        for (int i = 0; i < 4; i++) {
            float va[4] = {av[i].x, av[i].y, av[i].z, av[i].w};
            float vb[4] = {bv[i].x, bv[i].y, bv[i].z, bv[i].w};
            __nv_bfloat16 ah[4], al[4], bh[4], bl[4];
#pragma unroll
            for (int j = 0; j < 4; j++) {
                ah[j] = __float2bfloat16(va[j]);
                al[j] = __float2bfloat16(va[j] - __bfloat162float(ah[j]));
                bh[j] = __float2bfloat16(vb[j]);
                bl[j] = __float2bfloat16(vb[j] - __bfloat162float(bh[j]));
            }
            int off = srow[i] * PADK + sc4[i];
            *(uint2*)&As_hi[off] = make_uint2(pack_bf16(ah[0], ah[1]), pack_bf16(ah[2], ah[3]));
            *(uint2*)&As_lo[off] = make_uint2(pack_bf16(al[0], al[1]), pack_bf16(al[2], al[3]));
            *(uint2*)&Bs_hi[off] = make_uint2(pack_bf16(bh[0], bh[1]), pack_bf16(bh[2], bh[3]));
            *(uint2*)&Bs_lo[off] = make_uint2(pack_bf16(bl[0], bl[1]), pack_bf16(bl[2], bl[3]));
        }
        __syncthreads();

        // prefetch next chunk (LDGs in flight during compute)
        if (kt + 32 < K) {
#pragma unroll
            for (int i = 0; i < 4; i++) {
                av[i] = *(const float4*)(Ab + (size_t)srow[i] * K + kt + 32 + sc4[i]);
                bv[i] = *(const float4*)(Wb + (size_t)srow[i] * K + kt + 32 + sc4[i]);
            }
        }

#pragma unroll
        for (int k0 = 0; k0 < 32; k0 += 16) {
            unsigned ah[2][4], al[2][4];
#pragma unroll
            for (int mi = 0; mi < 2; mi++) {
                int rb = wm * 32 + mi * 16;
                int o00 = (rb + g) * PADK + k0 + 2 * t;
                int o10 = (rb + g + 8) * PADK + k0 + 2 * t;
                ah[mi][0] = *(const unsigned*)&As_hi[o00];
                ah[mi][1] = *(const unsigned*)&As_hi[o10];
                ah[mi][2] = *(const unsigned*)&As_hi[o00 + 8];
                ah[mi][3] = *(const unsigned*)&As_hi[o10 + 8];
                al[mi][0] = *(const unsigned*)&As_lo[o00];
                al[mi][1] = *(const unsigned*)&As_lo[o10];
                al[mi][2] = *(const unsigned*)&As_lo[o00 + 8];
                al[mi][3] = *(const unsigned*)&As_lo[o10 + 8];
            }
#pragma unroll
            for (int ni = 0; ni < 8; ni++) {
                int nb = wn * 64 + ni * 8;
                int ob = (nb + g) * PADK + k0 + 2 * t;
                unsigned bh[2], bl[2];
                bh[0] = *(const unsigned*)&Bs_hi[ob];
                bh[1] = *(const unsigned*)&Bs_hi[ob + 8];
                bl[0] = *(const unsigned*)&Bs_lo[ob];
                bl[1] = *(const unsigned*)&Bs_lo[ob + 8];
#pragma unroll
                for (int mi = 0; mi < 2; mi++) {
                    mma16816(acc[mi][ni], ah[mi], bh);
                    mma16816(acc[mi][ni], al[mi], bh);
                    mma16816(acc[mi][ni], ah[mi], bl);
                }
            }
        }
        __syncthreads();
    }

    // epilogue: bias + store (float2 per fragment row-pair)
#pragma unroll
    for (int mi = 0; mi < 2; mi++) {
#pragma unroll
        for (int ni = 0; ni < 8; ni++) {
            int col = blockIdx.x * 128 + wn * 64 + ni * 8 + 2 * t;
            float b0 = bias[col], b1 = bias[col + 1];
            size_t row0 = (size_t)blockIdx.y * 128 + wm * 32 + mi * 16 + g;
            *(float2*)(C + row0 * N + col) =
                make_float2(acc[mi][ni][0] + b0, acc[mi][ni][1] + b1);
            *(float2*)(C + (row0 + 8) * N + col) =
                make_float2(acc[mi][ni][2] + b0, acc[mi][ni][3] + b1);
        }
    }
}

// ---------------------------------------------------------------------------
// LayerNorm + 2D RoPE on Q, in place. One warp per (b, s, h) head-chunk.
// ---------------------------------------------------------------------------
__global__ void ln_rope_q(float* __restrict__ q,
                          const float* __restrict__ g, const float* __restrict__ bt)
{
    int gw = (blockIdx.x * blockDim.x + threadIdx.x) >> 5;
    int lane = threadIdx.x & 31;
    if (gw >= BB * S1 * NH) return;
    float2* p = (float2*)(q + (size_t)gw * HD);
    float2 v = p[lane];
    float sum = v.x + v.y;
    float sq = v.x * v.x + v.y * v.y;
#pragma unroll
    for (int o = 16; o; o >>= 1) {
        sum += __shfl_xor_sync(0xffffffffu, sum, o);
        sq  += __shfl_xor_sync(0xffffffffu, sq, o);
    }
    float mu = sum * (1.0f / HD);
    float var = sq * (1.0f / HD) - mu * mu;
    float rstd = rsqrtf(var + EPSF);
    float e  = (v.x - mu) * rstd * g[2 * lane]     + bt[2 * lane];
    float od = (v.y - mu) * rstd * g[2 * lane + 1] + bt[2 * lane + 1];

    int s = (gw / NH) & (S1 - 1);
    int hh = s >> 6, ww = s & 63;
    int t = lane >> 1;
    float inv = exp10f(-0.25f * (float)t);
    float ang = ((lane & 1) ? (float)ww : (float)hh) * inv;
    float n = rintf(ang * 0.15915494309189535f);
    ang -= n * 6.283185307179586f;
    float sn, cs;
    sincosf(ang, &sn, &cs);
    p[lane] = make_float2(e * cs - od * sn, e * sn + od * cs);
}

// LayerNorm on K, in place. One warp per (b, s2, h).
__global__ void ln_k(float* __restrict__ kv,
                     const float* __restrict__ g, const float* __restrict__ bt)
{
    int gw = (blockIdx.x * blockDim.x + threadIdx.x) >> 5;
    int lane = threadIdx.x & 31;
    if (gw >= BB * S2 * NH) return;
    int row = gw / NH, h = gw % NH;
    float2* p = (float2*)(kv + (size_t)row * KVD + h * HD);
    float2 v = p[lane];
    float sum = v.x + v.y;
    float sq = v.x * v.x + v.y * v.y;
#pragma unroll
    for (int o = 16; o; o >>= 1) {
        sum += __shfl_xor_sync(0xffffffffu, sum, o);
        sq  += __shfl_xor_sync(0xffffffffu, sq, o);
    }
    float mu = sum * (1.0f / HD);
    float var = sq * (1.0f / HD) - mu * mu;
    float rstd = rsqrtf(var + EPSF);
    float e  = (v.x - mu) * rstd * g[2 * lane]     + bt[2 * lane];
    float od = (v.y - mu) * rstd * g[2 * lane + 1] + bt[2 * lane + 1];
    p[lane] = make_float2(e, od);
}

// ---------------------------------------------------------------------------
// Attention (fp32 SIMT): one block = 128 query rows of one (b,h). S2=256 keys.
// ---------------------------------------------------------------------------
__global__ __launch_bounds__(256) void attention_kernel(
    const float* __restrict__ q, const float* __restrict__ kv,
    float* __restrict__ out)
{
    extern __shared__ float sm[];
    float* Qs = sm;
    float* Ks = sm + AR * HD;
    float* Ss = Ks + S2 * 65;
    int bh = blockIdx.y;
    int b = bh >> 4, h = bh & 15;
    int r0 = blockIdx.x * AR;
    int tid = threadIdx.x;

    for (int i = tid; i < AR * HD; i += 256) {
        int r = i >> 6, d = i & 63;
        Qs[i] = q[(((size_t)b * S1 + r0 + r) * NH + h) * HD + d];
    }
    for (int i = tid; i < S2 * HD; i += 256) {
        int k = i >> 6, d = i & 63;
        Ks[k * 65 + d] = kv[((size_t)b * S2 + k) * KVD + h * HD + d];
    }
    __syncthreads();

    float kreg[64];
#pragma unroll
    for (int d = 0; d < 64; d++) kreg[d] = Ks[tid * 65 + d];

    for (int r = 0; r < AR; r += 2) {
        const float* q0 = Qs + r * 64;
        const float* q1 = q0 + 64;
        float a0 = 0, a1 = 0, c0 = 0, c1 = 0;
#pragma unroll
        for (int d = 0; d < 64; d += 2) {
            a0 += q0[d] * kreg[d];     a1 += q0[d + 1] * kreg[d + 1];
            c0 += q1[d] * kreg[d];     c1 += q1[d + 1] * kreg[d + 1];
        }
        Ss[r * 256 + tid]       = (a0 + a1) * SCALEF;
        Ss[(r + 1) * 256 + tid] = (c0 + c1) * SCALEF;
    }
    __syncthreads();

    int wid = tid >> 5, lane = tid & 31;
    for (int r = wid; r < AR; r += 8) {
        float* srow = Ss + r * 256;
        float vals[8];
        float m = -1e30f;
#pragma unroll
        for (int i = 0; i < 8; i++) { vals[i] = srow[lane + 32 * i]; m = fmaxf(m, vals[i]); }
#pragma unroll
        for (int o = 16; o; o >>= 1) m = fmaxf(m, __shfl_xor_sync(0xffffffffu, m, o));
        float l = 0;
#pragma unroll
        for (int i = 0; i < 8; i++) { vals[i] = __expf(vals[i] - m); l += vals[i]; }
#pragma unroll
        for (int o = 16; o; o >>= 1) l += __shfl_xor_sync(0xffffffffu, l, o);
        float rl = 1.0f / l;
#pragma unroll
        for (int i = 0; i < 8; i++) srow[lane + 32 * i] = vals[i] * rl;
    }
    __syncthreads();

    for (int i = tid; i < S2 * HD; i += 256) {
        int k = i >> 6, d = i & 63;
        Ks[k * 65 + d] = kv[((size_t)b * S2 + k) * KVD + QD + h * HD + d];
    }
    __syncthreads();

    int d0 = lane, d1 = lane + 32;
    for (int i = 0; i < 16; i++) {
        int r = wid + 8 * i;
        const float* srow = Ss + r * 256;
        float acc0 = 0, acc1 = 0;
#pragma unroll 8
        for (int k = 0; k < 256; k++) {
            float pv = srow[k];
            acc0 += pv * Ks[k * 65 + d0];
            acc1 += pv * Ks[k * 65 + d1];
        }
        size_t ob = (((size_t)b * S1 + r0 + r) * NH + h) * HD;
        out[ob + d0] = acc0;
        out[ob + d1] = acc1;
    }
}

// ---------------------------------------------------------------------------
extern "C" void kernel_launch(void* const* d_in, const int* in_sizes, int n_in,
                              void* d_out, int out_size)
{
    (void)in_sizes; (void)n_in; (void)out_size;
    const float* x   = (const float*)d_in[0];
    const float* y   = (const float*)d_in[1];
    const float* wq  = (const float*)d_in[2];
    const float* bq  = (const float*)d_in[3];
    const float* wkv = (const float*)d_in[4];
    const float* bkv = (const float*)d_in[5];
    const float* wo  = (const float*)d_in[6];
    const float* bo  = (const float*)d_in[7];
    const float* qng = (const float*)d_in[8];
    const float* qnb = (const float*)d_in[9];
    const float* kng = (const float*)d_in[10];
    const float* knb = (const float*)d_in[11];
    float* out = (float*)d_out;

    float *qbuf, *kvbuf, *abuf;
    cudaGetSymbolAddress((void**)&qbuf, g_q);
    cudaGetSymbolAddress((void**)&kvbuf, g_kv);
    cudaGetSymbolAddress((void**)&abuf, g_att);

    // 1) Q = x @ wq^T + bq
    gemm_bias_tc<<<dim3(QD / 128, (BB * S1) / 128), 256>>>(x, wq, bq, qbuf, BB * S1, QD, QD);
    // 2) KV = y @ wkv^T + bkv
    gemm_bias_tc<<<dim3(KVD / 128, (BB * S2) / 128), 256>>>(y, wkv, bkv, kvbuf, BB * S2, KVD, KVD);
    // 3) LN + RoPE on Q
    ln_rope_q<<<(BB * S1 * NH) / 4, 128>>>(qbuf, qng, qnb);
    // 4) LN on K
    ln_k<<<(BB * S2 * NH) / 4, 128>>>(kvbuf, kng, knb);
    // 5) attention
    {
        size_t smem = (size_t)(AR * HD + S2 * 65 + AR * S2) * sizeof(float);
        cudaFuncSetAttribute(attention_kernel,
                             cudaFuncAttributeMaxDynamicSharedMemorySize, (int)smem);
        attention_kernel<<<dim3(S1 / AR, BB * NH), 256, smem>>>(qbuf, kvbuf, abuf);
    }
    // 6) out = att @ wo^T + bo
    gemm_bias_tc<<<dim3(QD / 128, (BB * S1) / 128), 256>>>(abuf, wo, bo, out, BB * S1, QD, QD);
}